// round 8
// baseline (speedup 1.0000x reference)
#include <cuda_runtime.h>

#define NB 16384            // batch
#define NPARAM 811
#define P_W1 0
#define P_B1 27
#define P_W2 30
#define P_B2 192
#define P_W3 198
#define P_B3 360
#define P_W4 363
#define P_B4 795

// Scratch (param-major [idx][NB]: lane-pair==sample-pair -> aligned float2)
__device__ float g_h [16  * NB];
__device__ float g_w [NPARAM * NB];
__device__ float g_p1[507 * NB];   // pooled conv1: 13*13*3
__device__ float g_p2[150 * NB];   // pooled conv2: 5*5*6
__device__ float g_a3[27  * NB];   // relu conv3:   3*3*3

union F2U { float2 f; unsigned long long u; };
__device__ __forceinline__ float2 ffma2(float2 a, float2 b, float2 c) {
    F2U A, B, C, D; A.f = a; B.f = b; C.f = c;
    asm("fma.rn.f32x2 %0, %1, %2, %3;" : "=l"(D.u) : "l"(A.u), "l"(B.u), "l"(C.u));
    return D.f;
}
__device__ __forceinline__ float2 ld2(const float* p) {
    return *reinterpret_cast<const float2*>(p);
}
__device__ __forceinline__ void st2(float* p, float2 v) {
    *reinterpret_cast<float2*>(p) = v;
}
__device__ __forceinline__ float2 max2(float2 a, float2 b) {
    return make_float2(fmaxf(a.x, b.x), fmaxf(a.y, b.y));
}
__device__ __forceinline__ float2 relu2(float2 a) {
    return make_float2(fmaxf(a.x, 0.f), fmaxf(a.y, 0.f));
}

// ---------------------------------------------------------------------------
// Kernel 0: MLP hidden layers (scalar; tiny)
// ---------------------------------------------------------------------------
__global__ __launch_bounds__(256) void k_mlp_h(
    const float* __restrict__ state,
    const float* __restrict__ W1, const float* __restrict__ b1,
    const float* __restrict__ W2, const float* __restrict__ b2)
{
    int b = blockIdx.x * 256 + threadIdx.x;
    float st[16];
    const float4* sp = reinterpret_cast<const float4*>(state + b * 16);
#pragma unroll
    for (int q = 0; q < 4; q++) {
        float4 v = sp[q];
        st[4*q+0] = v.x; st[4*q+1] = v.y; st[4*q+2] = v.z; st[4*q+3] = v.w;
    }
    float h1[16];
#pragma unroll
    for (int i = 0; i < 16; i++) h1[i] = __ldg(&b1[i]);
#pragma unroll
    for (int k = 0; k < 16; k++) {
        float s = st[k];
#pragma unroll
        for (int i = 0; i < 16; i++) h1[i] += s * __ldg(&W1[k*16 + i]);
    }
#pragma unroll
    for (int i = 0; i < 16; i++) h1[i] = fmaxf(h1[i], 0.f);

    float h2[16];
#pragma unroll
    for (int i = 0; i < 16; i++) h2[i] = __ldg(&b2[i]);
#pragma unroll
    for (int k = 0; k < 16; k++) {
        float s = h1[k];
#pragma unroll
        for (int i = 0; i < 16; i++) h2[i] += s * __ldg(&W2[k*16 + i]);
    }
#pragma unroll
    for (int i = 0; i < 16; i++) g_h[i*NB + b] = fmaxf(h2[i], 0.f);
}

// ---------------------------------------------------------------------------
// Kernel 1: MLP layer 3. 2 sample-pairs per thread (4 samples), float4 I/O,
// each smem weight LDS feeds 2 FFMA2. Block 256 = 32 lanes x 8 j-rows.
// ---------------------------------------------------------------------------
__global__ __launch_bounds__(256, 2) void k_mlp3(
    const float* __restrict__ W3, const float* __restrict__ b3)
{
    __shared__ float2 W3s[16 * 64];
    __shared__ float  b3s[64];

    int tid = threadIdx.x;
    int j0  = blockIdx.y * 64;
    int b0  = blockIdx.x * 128;       // 128 samples per block

    for (int idx = tid; idx < 16 * 64; idx += 256) {
        int k = idx >> 6, jj = idx & 63;
        int j = j0 + jj;
        float w = (j < NPARAM) ? W3[k * NPARAM + j] : 0.f;
        W3s[idx] = make_float2(w, w);
    }
    if (tid < 64) {
        int j = j0 + tid;
        b3s[tid] = (j < NPARAM) ? b3[j] : 0.f;
    }
    __syncthreads();

    int s  = tid & 31;
    int jr = tid >> 5;
    int b  = b0 + 4 * s;              // 4 consecutive samples

    float2 h0[16], h1[16];
#pragma unroll
    for (int k = 0; k < 16; k++) {
        float4 v = *reinterpret_cast<const float4*>(&g_h[k * NB + b]);
        h0[k] = make_float2(v.x, v.y);
        h1[k] = make_float2(v.z, v.w);
    }

    float2 acc0[8], acc1[8];
#pragma unroll
    for (int i = 0; i < 8; i++) {
        float bb = b3s[jr * 8 + i];
        acc0[i] = make_float2(bb, bb);
        acc1[i] = make_float2(bb, bb);
    }
#pragma unroll
    for (int k = 0; k < 16; k++) {
#pragma unroll
        for (int i = 0; i < 8; i++) {
            float2 w = W3s[k * 64 + jr * 8 + i];
            acc0[i] = ffma2(h0[k], w, acc0[i]);
            acc1[i] = ffma2(h1[k], w, acc1[i]);
        }
    }
#pragma unroll
    for (int i = 0; i < 8; i++) {
        int j = j0 + jr * 8 + i;
        if (j < NPARAM) {
            float4 o = make_float4(acc0[i].x, acc0[i].y, acc1[i].x, acc1[i].y);
            *reinterpret_cast<float4*>(&g_w[j * NB + b]) = o;
        }
    }
}

// ---------------------------------------------------------------------------
// Kernel 2: conv1(3x3,1->3)+relu+maxpool2. NPR pooled rows per thread
// (2 for y<6, 1 for the tail row 12). Rolling 2-col window, pc loop rolled.
// ---------------------------------------------------------------------------
template<int NPR>
__device__ __forceinline__ void conv1_body(const float* __restrict__ img,
                                           int b, int pr0)
{
    float2 wt[27], bias[3];
#pragma unroll
    for (int p = 0; p < 27; p++) wt[p] = ld2(&g_w[(P_W1 + p) * NB + b]);
#pragma unroll
    for (int c = 0; c < 3; c++)  bias[c] = ld2(&g_w[(P_B1 + c) * NB + b]);

    const int R = 2 * NPR + 2;                       // 6 or 4 image rows
    const float* imrow = img + (2 * pr0 * 28) * NB + b;

    float2 win[2 * NPR + 2][4];
#pragma unroll
    for (int i = 0; i < R; i++) {
        win[i][0] = ld2(&imrow[(i * 28 + 0) * NB]);
        win[i][1] = ld2(&imrow[(i * 28 + 1) * NB]);
    }

#pragma unroll 1
    for (int pc = 0; pc < 13; pc++) {
#pragma unroll
        for (int i = 0; i < R; i++) {
            win[i][2] = ld2(&imrow[(i * 28 + 2 * pc + 2) * NB]);
            win[i][3] = ld2(&imrow[(i * 28 + 2 * pc + 3) * NB]);
        }
        float2 acc[NPR][2][2][3];
#pragma unroll
        for (int pr = 0; pr < NPR; pr++)
#pragma unroll
            for (int dr = 0; dr < 2; dr++)
#pragma unroll
                for (int dc = 0; dc < 2; dc++)
#pragma unroll
                    for (int co = 0; co < 3; co++) acc[pr][dr][dc][co] = bias[co];

#pragma unroll
        for (int ky = 0; ky < 3; ky++)
#pragma unroll
            for (int kx = 0; kx < 3; kx++) {
#pragma unroll
                for (int pr = 0; pr < NPR; pr++)
#pragma unroll
                    for (int dr = 0; dr < 2; dr++)
#pragma unroll
                        for (int dc = 0; dc < 2; dc++) {
                            float2 v = win[2 * pr + dr + ky][dc + kx];
#pragma unroll
                            for (int co = 0; co < 3; co++)
                                acc[pr][dr][dc][co] =
                                    ffma2(v, wt[co * 9 + ky * 3 + kx],
                                          acc[pr][dr][dc][co]);
                        }
            }
#pragma unroll
        for (int pr = 0; pr < NPR; pr++)
#pragma unroll
            for (int co = 0; co < 3; co++) {
                float2 m = max2(max2(acc[pr][0][0][co], acc[pr][0][1][co]),
                                max2(acc[pr][1][0][co], acc[pr][1][1][co]));
                st2(&g_p1[(((pr0 + pr) * 13 + pc) * 3 + co) * NB + b], relu2(m));
            }
#pragma unroll
        for (int i = 0; i < R; i++) {
            win[i][0] = win[i][2];
            win[i][1] = win[i][3];
        }
    }
}

__global__ __launch_bounds__(128, 3) void k_conv1(const float* __restrict__ img)
{
    int b = (blockIdx.x * 128 + threadIdx.x) * 2;
    int y = blockIdx.y;               // 0..6
    if (y < 6) conv1_body<2>(img, b, 2 * y);
    else       conv1_body<1>(img, b, 12);
}

// ---------------------------------------------------------------------------
// Kernel 3: conv2(3x3,3->6)+relu+maxpool2. ci-outer + pc-tile (3+2),
// 64-thr blocks, 8 blocks/SM (16 warps). blockIdx.z = coh*2 + pct.
// ---------------------------------------------------------------------------
template<int NPC>
__device__ __forceinline__ void conv2_body(int b, int p2, int coh, int pcs)
{
    float2 acc[2][NPC][2][2];
#pragma unroll
    for (int c = 0; c < 2; c++) {
        float2 bb = ld2(&g_w[(P_B2 + coh * 2 + c) * NB + b]);
#pragma unroll
        for (int t = 0; t < NPC; t++)
#pragma unroll
            for (int dr = 0; dr < 2; dr++)
#pragma unroll
                for (int dc = 0; dc < 2; dc++) acc[c][t][dr][dc] = bb;
    }

    const float* p1 = g_p1 + (2 * p2 * 13 * 3) * NB + b;

#pragma unroll
    for (int ci = 0; ci < 3; ci++) {
        float2 wt[2][9];
#pragma unroll
        for (int c = 0; c < 2; c++)
#pragma unroll
            for (int t = 0; t < 9; t++)
                wt[c][t] = ld2(&g_w[(P_W2 + (coh * 2 + c) * 27 + t * 3 + ci) * NB + b]);

        float2 win[4][4];
#pragma unroll
        for (int i = 0; i < 4; i++) {
            win[i][0] = ld2(&p1[((i * 13 + 2 * pcs + 0) * 3 + ci) * NB]);
            win[i][1] = ld2(&p1[((i * 13 + 2 * pcs + 1) * 3 + ci) * NB]);
        }

#pragma unroll
        for (int t = 0; t < NPC; t++) {
            int pc = pcs + t;
#pragma unroll
            for (int i = 0; i < 4; i++) {
                win[i][2] = ld2(&p1[((i * 13 + 2 * pc + 2) * 3 + ci) * NB]);
                win[i][3] = ld2(&p1[((i * 13 + 2 * pc + 3) * 3 + ci) * NB]);
            }
#pragma unroll
            for (int ky = 0; ky < 3; ky++)
#pragma unroll
                for (int kx = 0; kx < 3; kx++) {
#pragma unroll
                    for (int c = 0; c < 2; c++) {
                        float2 w = wt[c][ky * 3 + kx];
#pragma unroll
                        for (int dr = 0; dr < 2; dr++)
#pragma unroll
                            for (int dc = 0; dc < 2; dc++)
                                acc[c][t][dr][dc] =
                                    ffma2(win[dr + ky][dc + kx], w, acc[c][t][dr][dc]);
                    }
                }
#pragma unroll
            for (int i = 0; i < 4; i++) {
                win[i][0] = win[i][2];
                win[i][1] = win[i][3];
            }
        }
    }

#pragma unroll
    for (int t = 0; t < NPC; t++)
#pragma unroll
        for (int c = 0; c < 2; c++) {
            float2 m = max2(max2(acc[c][t][0][0], acc[c][t][0][1]),
                            max2(acc[c][t][1][0], acc[c][t][1][1]));
            st2(&g_p2[((p2 * 5 + pcs + t) * 6 + coh * 2 + c) * NB + b], relu2(m));
        }
}

__global__ __launch_bounds__(64, 8) void k_conv2()
{
    int b   = (blockIdx.x * 64 + threadIdx.x) * 2;
    int p2  = blockIdx.y;             // 0..4
    int z   = blockIdx.z;             // 0..5
    int coh = z >> 1;                 // 0..2
    int pct = z & 1;                  // 0: pc 0-2, 1: pc 3-4
    if (pct == 0) conv2_body<3>(b, p2, coh, 0);
    else          conv2_body<2>(b, p2, coh, 3);
}

// ---------------------------------------------------------------------------
// Kernel 4: conv3(3x3,6->3)+relu. blockIdx.y = co*3 + r (9-way grid split).
// ---------------------------------------------------------------------------
__global__ __launch_bounds__(128, 3) void k_conv3()
{
    int b  = (blockIdx.x * 128 + threadIdx.x) * 2;
    int co = blockIdx.y / 3;           // 0..2
    int r  = blockIdx.y % 3;           // output row 0..2

    float2 bias = ld2(&g_w[(P_B3 + co) * NB + b]);
    float2 acc[3];
#pragma unroll
    for (int oc = 0; oc < 3; oc++) acc[oc] = bias;

#pragma unroll
    for (int h = 0; h < 2; h++) {
        float2 wt[27];
#pragma unroll
        for (int t = 0; t < 9; t++)
#pragma unroll
            for (int c3 = 0; c3 < 3; c3++)
                wt[t * 3 + c3] =
                    ld2(&g_w[(P_W3 + co * 54 + t * 6 + h * 3 + c3) * NB + b]);

        float2 win[3][5][3];
#pragma unroll
        for (int i = 0; i < 3; i++)
#pragma unroll
            for (int c = 0; c < 5; c++)
#pragma unroll
                for (int c3 = 0; c3 < 3; c3++)
                    win[i][c][c3] =
                        ld2(&g_p2[(((r + i) * 5 + c) * 6 + h * 3 + c3) * NB + b]);

#pragma unroll
        for (int ky = 0; ky < 3; ky++)
#pragma unroll
            for (int kx = 0; kx < 3; kx++)
#pragma unroll
                for (int c3 = 0; c3 < 3; c3++) {
                    float2 w = wt[(ky * 3 + kx) * 3 + c3];
#pragma unroll
                    for (int oc = 0; oc < 3; oc++)
                        acc[oc] = ffma2(win[ky][oc + kx][c3], w, acc[oc]);
                }
    }
#pragma unroll
    for (int oc = 0; oc < 3; oc++)
        st2(&g_a3[((r * 3 + oc) * 3 + co) * NB + b], relu2(acc[oc]));
}

// ---------------------------------------------------------------------------
// Kernel 5: conv4(1x1 out) + residual. 4 couts per block, float4 stores.
// ---------------------------------------------------------------------------
__global__ __launch_bounds__(128) void k_conv4(
    const float* __restrict__ state, float* __restrict__ out)
{
    int tid = threadIdx.x;
    int b   = (blockIdx.x * 128 + tid) * 2;
    int cg  = blockIdx.y;              // couts 4cg..4cg+3

    float2 a3[27];
#pragma unroll
    for (int t = 0; t < 27; t++) a3[t] = ld2(&g_a3[t * NB + b]);

    float2 acc[4];
#pragma unroll
    for (int q = 0; q < 4; q++) {
        int co = cg * 4 + q;
        acc[q] = ld2(&g_w[(P_B4 + co) * NB + b]);
#pragma unroll
        for (int t = 0; t < 27; t++)
            acc[q] = ffma2(a3[t], ld2(&g_w[(P_W4 + co * 27 + t) * NB + b]), acc[q]);
    }

    const float4* s0 = reinterpret_cast<const float4*>(state + b * 16 + 4 * cg);
    const float4* s1 = reinterpret_cast<const float4*>(state + (b + 1) * 16 + 4 * cg);
    float4 v0 = *s0, v1 = *s1;
    float4 o0 = make_float4(v0.x + acc[0].x, v0.y + acc[1].x,
                            v0.z + acc[2].x, v0.w + acc[3].x);
    float4 o1 = make_float4(v1.x + acc[0].y, v1.y + acc[1].y,
                            v1.z + acc[2].y, v1.w + acc[3].y);
    *reinterpret_cast<float4*>(out + b * 16 + 4 * cg)       = o0;
    *reinterpret_cast<float4*>(out + (b + 1) * 16 + 4 * cg) = o1;
}

// ---------------------------------------------------------------------------
extern "C" void kernel_launch(void* const* d_in, const int* in_sizes, int n_in,
                              void* d_out, int out_size)
{
    const float* image = (const float*)d_in[0];
    const float* state = (const float*)d_in[1];
    const float* W1    = (const float*)d_in[2];
    const float* b1    = (const float*)d_in[3];
    const float* W2    = (const float*)d_in[4];
    const float* b2    = (const float*)d_in[5];
    const float* W3    = (const float*)d_in[6];
    const float* b3    = (const float*)d_in[7];
    float* out = (float*)d_out;

    k_mlp_h<<<NB / 256, 256>>>(state, W1, b1, W2, b2);
    k_mlp3 <<<dim3(NB / 128, 13), 256>>>(W3, b3);
    k_conv1<<<dim3(NB / 256, 7), 128>>>(image);
    k_conv2<<<dim3(NB / 128, 5, 6), 64>>>();
    k_conv3<<<dim3(NB / 256, 9), 128>>>();
    k_conv4<<<dim3(NB / 256, 4), 128>>>(state, out);
}

// round 10
// speedup vs baseline: 1.1133x; 1.1133x over previous
#include <cuda_runtime.h>

#define NB 16384            // batch
#define NPARAM 811
#define P_W1 0
#define P_B1 27
#define P_W2 30
#define P_B2 192
#define P_W3 198
#define P_B3 360
#define P_W4 363
#define P_B4 795

// Scratch (param-major [idx][NB]: lane-pair==sample-pair -> aligned float2)
__device__ float g_h [16  * NB];
__device__ float g_w [NPARAM * NB];
__device__ float g_p1[507 * NB];   // pooled conv1: 13*13*3
__device__ float g_p2[150 * NB];   // pooled conv2: 5*5*6
__device__ float g_a3[27  * NB];   // relu conv3:   3*3*3

union F2U { float2 f; unsigned long long u; };
__device__ __forceinline__ float2 ffma2(float2 a, float2 b, float2 c) {
    F2U A, B, C, D; A.f = a; B.f = b; C.f = c;
    asm("fma.rn.f32x2 %0, %1, %2, %3;" : "=l"(D.u) : "l"(A.u), "l"(B.u), "l"(C.u));
    return D.f;
}
__device__ __forceinline__ float2 ld2(const float* p) {
    return *reinterpret_cast<const float2*>(p);
}
__device__ __forceinline__ void st2(float* p, float2 v) {
    *reinterpret_cast<float2*>(p) = v;
}
__device__ __forceinline__ float2 max2(float2 a, float2 b) {
    return make_float2(fmaxf(a.x, b.x), fmaxf(a.y, b.y));
}
__device__ __forceinline__ float2 relu2(float2 a) {
    return make_float2(fmaxf(a.x, 0.f), fmaxf(a.y, 0.f));
}

// ---------------------------------------------------------------------------
// Kernel 0: MLP hidden layers (scalar; tiny)
// ---------------------------------------------------------------------------
__global__ __launch_bounds__(256) void k_mlp_h(
    const float* __restrict__ state,
    const float* __restrict__ W1, const float* __restrict__ b1,
    const float* __restrict__ W2, const float* __restrict__ b2)
{
    int b = blockIdx.x * 256 + threadIdx.x;
    float st[16];
    const float4* sp = reinterpret_cast<const float4*>(state + b * 16);
#pragma unroll
    for (int q = 0; q < 4; q++) {
        float4 v = sp[q];
        st[4*q+0] = v.x; st[4*q+1] = v.y; st[4*q+2] = v.z; st[4*q+3] = v.w;
    }
    float h1[16];
#pragma unroll
    for (int i = 0; i < 16; i++) h1[i] = __ldg(&b1[i]);
#pragma unroll
    for (int k = 0; k < 16; k++) {
        float s = st[k];
#pragma unroll
        for (int i = 0; i < 16; i++) h1[i] += s * __ldg(&W1[k*16 + i]);
    }
#pragma unroll
    for (int i = 0; i < 16; i++) h1[i] = fmaxf(h1[i], 0.f);

    float h2[16];
#pragma unroll
    for (int i = 0; i < 16; i++) h2[i] = __ldg(&b2[i]);
#pragma unroll
    for (int k = 0; k < 16; k++) {
        float s = h1[k];
#pragma unroll
        for (int i = 0; i < 16; i++) h2[i] += s * __ldg(&W2[k*16 + i]);
    }
#pragma unroll
    for (int i = 0; i < 16; i++) g_h[i*NB + b] = fmaxf(h2[i], 0.f);
}

// ---------------------------------------------------------------------------
// Kernel 1: MLP layer 3. 2 sample-pairs per thread (4 samples), float4 I/O,
// each smem weight LDS feeds 2 FFMA2. Block 256 = 32 lanes x 8 j-rows.
// ---------------------------------------------------------------------------
__global__ __launch_bounds__(256, 2) void k_mlp3(
    const float* __restrict__ W3, const float* __restrict__ b3)
{
    __shared__ float2 W3s[16 * 64];
    __shared__ float  b3s[64];

    int tid = threadIdx.x;
    int j0  = blockIdx.y * 64;
    int b0  = blockIdx.x * 128;       // 128 samples per block

    for (int idx = tid; idx < 16 * 64; idx += 256) {
        int k = idx >> 6, jj = idx & 63;
        int j = j0 + jj;
        float w = (j < NPARAM) ? W3[k * NPARAM + j] : 0.f;
        W3s[idx] = make_float2(w, w);
    }
    if (tid < 64) {
        int j = j0 + tid;
        b3s[tid] = (j < NPARAM) ? b3[j] : 0.f;
    }
    __syncthreads();

    int s  = tid & 31;
    int jr = tid >> 5;
    int b  = b0 + 4 * s;              // 4 consecutive samples

    float2 h0[16], h1[16];
#pragma unroll
    for (int k = 0; k < 16; k++) {
        float4 v = *reinterpret_cast<const float4*>(&g_h[k * NB + b]);
        h0[k] = make_float2(v.x, v.y);
        h1[k] = make_float2(v.z, v.w);
    }

    float2 acc0[8], acc1[8];
#pragma unroll
    for (int i = 0; i < 8; i++) {
        float bb = b3s[jr * 8 + i];
        acc0[i] = make_float2(bb, bb);
        acc1[i] = make_float2(bb, bb);
    }
#pragma unroll
    for (int k = 0; k < 16; k++) {
#pragma unroll
        for (int i = 0; i < 8; i++) {
            float2 w = W3s[k * 64 + jr * 8 + i];
            acc0[i] = ffma2(h0[k], w, acc0[i]);
            acc1[i] = ffma2(h1[k], w, acc1[i]);
        }
    }
#pragma unroll
    for (int i = 0; i < 8; i++) {
        int j = j0 + jr * 8 + i;
        if (j < NPARAM) {
            float4 o = make_float4(acc0[i].x, acc0[i].y, acc1[i].x, acc1[i].y);
            *reinterpret_cast<float4*>(&g_w[j * NB + b]) = o;
        }
    }
}

// ---------------------------------------------------------------------------
// Kernel 2: conv1(3x3,1->3)+relu+maxpool2. NPR pooled rows per thread
// (2 for y<6, 1 for the tail row 12). Rolling 2-col window, pc loop rolled.
// ---------------------------------------------------------------------------
template<int NPR>
__device__ __forceinline__ void conv1_body(const float* __restrict__ img,
                                           int b, int pr0)
{
    float2 wt[27], bias[3];
#pragma unroll
    for (int p = 0; p < 27; p++) wt[p] = ld2(&g_w[(P_W1 + p) * NB + b]);
#pragma unroll
    for (int c = 0; c < 3; c++)  bias[c] = ld2(&g_w[(P_B1 + c) * NB + b]);

    const int R = 2 * NPR + 2;                       // 6 or 4 image rows
    const float* imrow = img + (2 * pr0 * 28) * NB + b;

    float2 win[2 * NPR + 2][4];
#pragma unroll
    for (int i = 0; i < R; i++) {
        win[i][0] = ld2(&imrow[(i * 28 + 0) * NB]);
        win[i][1] = ld2(&imrow[(i * 28 + 1) * NB]);
    }

#pragma unroll 1
    for (int pc = 0; pc < 13; pc++) {
#pragma unroll
        for (int i = 0; i < R; i++) {
            win[i][2] = ld2(&imrow[(i * 28 + 2 * pc + 2) * NB]);
            win[i][3] = ld2(&imrow[(i * 28 + 2 * pc + 3) * NB]);
        }
        float2 acc[NPR][2][2][3];
#pragma unroll
        for (int pr = 0; pr < NPR; pr++)
#pragma unroll
            for (int dr = 0; dr < 2; dr++)
#pragma unroll
                for (int dc = 0; dc < 2; dc++)
#pragma unroll
                    for (int co = 0; co < 3; co++) acc[pr][dr][dc][co] = bias[co];

#pragma unroll
        for (int ky = 0; ky < 3; ky++)
#pragma unroll
            for (int kx = 0; kx < 3; kx++) {
#pragma unroll
                for (int pr = 0; pr < NPR; pr++)
#pragma unroll
                    for (int dr = 0; dr < 2; dr++)
#pragma unroll
                        for (int dc = 0; dc < 2; dc++) {
                            float2 v = win[2 * pr + dr + ky][dc + kx];
#pragma unroll
                            for (int co = 0; co < 3; co++)
                                acc[pr][dr][dc][co] =
                                    ffma2(v, wt[co * 9 + ky * 3 + kx],
                                          acc[pr][dr][dc][co]);
                        }
            }
#pragma unroll
        for (int pr = 0; pr < NPR; pr++)
#pragma unroll
            for (int co = 0; co < 3; co++) {
                float2 m = max2(max2(acc[pr][0][0][co], acc[pr][0][1][co]),
                                max2(acc[pr][1][0][co], acc[pr][1][1][co]));
                st2(&g_p1[(((pr0 + pr) * 13 + pc) * 3 + co) * NB + b], relu2(m));
            }
#pragma unroll
        for (int i = 0; i < R; i++) {
            win[i][0] = win[i][2];
            win[i][1] = win[i][3];
        }
    }
}

__global__ __launch_bounds__(128, 3) void k_conv1(const float* __restrict__ img)
{
    int b = (blockIdx.x * 128 + threadIdx.x) * 2;
    int y = blockIdx.y;               // 0..6
    if (y < 6) conv1_body<2>(img, b, 2 * y);
    else       conv1_body<1>(img, b, 12);
}

// ---------------------------------------------------------------------------
// Kernel 3: conv2(3x3,3->6)+relu+maxpool2, ci-outer (round-7 form, best
// measured). blockIdx.z = cout pair. ~168 regs -> 12 warps/SM.
// ---------------------------------------------------------------------------
__global__ __launch_bounds__(128, 3) void k_conv2()
{
    int b   = (blockIdx.x * 128 + threadIdx.x) * 2;
    int p2  = blockIdx.y;           // 0..4
    int coh = blockIdx.z;           // 0..2 -> couts 2*coh, 2*coh+1

    float2 acc[2][5][2][2];
#pragma unroll
    for (int c = 0; c < 2; c++) {
        float2 bb = ld2(&g_w[(P_B2 + coh * 2 + c) * NB + b]);
#pragma unroll
        for (int pc = 0; pc < 5; pc++)
#pragma unroll
            for (int dr = 0; dr < 2; dr++)
#pragma unroll
                for (int dc = 0; dc < 2; dc++) acc[c][pc][dr][dc] = bb;
    }

    const float* p1 = g_p1 + (2 * p2 * 13 * 3) * NB + b;  // rows 2p2..2p2+3

#pragma unroll
    for (int ci = 0; ci < 3; ci++) {
        float2 wt[2][9];
#pragma unroll
        for (int c = 0; c < 2; c++)
#pragma unroll
            for (int t = 0; t < 9; t++)
                wt[c][t] = ld2(&g_w[(P_W2 + (coh * 2 + c) * 27 + t * 3 + ci) * NB + b]);

        float2 win[4][4];
#pragma unroll
        for (int i = 0; i < 4; i++)
#pragma unroll
            for (int cc = 0; cc < 4; cc++)
                win[i][cc] = ld2(&p1[((i * 13 + cc) * 3 + ci) * NB]);

#pragma unroll
        for (int pc = 0; pc < 5; pc++) {
            if (pc > 0) {
#pragma unroll
                for (int i = 0; i < 4; i++) {
                    win[i][0] = win[i][2];
                    win[i][1] = win[i][3];
                    win[i][2] = ld2(&p1[((i * 13 + 2 * pc + 2) * 3 + ci) * NB]);
                    win[i][3] = ld2(&p1[((i * 13 + 2 * pc + 3) * 3 + ci) * NB]);
                }
            }
#pragma unroll
            for (int ky = 0; ky < 3; ky++)
#pragma unroll
                for (int kx = 0; kx < 3; kx++) {
#pragma unroll
                    for (int c = 0; c < 2; c++) {
                        float2 w = wt[c][ky * 3 + kx];
#pragma unroll
                        for (int dr = 0; dr < 2; dr++)
#pragma unroll
                            for (int dc = 0; dc < 2; dc++)
                                acc[c][pc][dr][dc] =
                                    ffma2(win[dr + ky][dc + kx], w, acc[c][pc][dr][dc]);
                    }
                }
        }
    }

#pragma unroll
    for (int pc = 0; pc < 5; pc++)
#pragma unroll
        for (int c = 0; c < 2; c++) {
            float2 m = max2(max2(acc[c][pc][0][0], acc[c][pc][0][1]),
                            max2(acc[c][pc][1][0], acc[c][pc][1][1]));
            st2(&g_p2[((p2 * 5 + pc) * 6 + coh * 2 + c) * NB + b], relu2(m));
        }
}

// ---------------------------------------------------------------------------
// Kernel 4: conv3(3x3,6->3)+relu. ci-OUTER: acc 3 f2 + per-ci win 15 f2
// + wt 9 f2 => ~80 regs, 16+ warps/SM. blockIdx.y = co*3 + r.
// ---------------------------------------------------------------------------
__global__ __launch_bounds__(128, 4) void k_conv3()
{
    int b  = (blockIdx.x * 128 + threadIdx.x) * 2;
    int co = blockIdx.y / 3;           // 0..2
    int r  = blockIdx.y % 3;           // output row 0..2

    float2 bias = ld2(&g_w[(P_B3 + co) * NB + b]);
    float2 acc[3];
#pragma unroll
    for (int oc = 0; oc < 3; oc++) acc[oc] = bias;

#pragma unroll
    for (int ci = 0; ci < 6; ci++) {
        float2 wt[9];
#pragma unroll
        for (int t = 0; t < 9; t++)
            wt[t] = ld2(&g_w[(P_W3 + co * 54 + t * 6 + ci) * NB + b]);

        float2 win[3][5];
#pragma unroll
        for (int i = 0; i < 3; i++)
#pragma unroll
            for (int c = 0; c < 5; c++)
                win[i][c] = ld2(&g_p2[(((r + i) * 5 + c) * 6 + ci) * NB + b]);

#pragma unroll
        for (int ky = 0; ky < 3; ky++)
#pragma unroll
            for (int kx = 0; kx < 3; kx++) {
                float2 w = wt[ky * 3 + kx];
#pragma unroll
                for (int oc = 0; oc < 3; oc++)
                    acc[oc] = ffma2(win[ky][oc + kx], w, acc[oc]);
            }
    }
#pragma unroll
    for (int oc = 0; oc < 3; oc++)
        st2(&g_a3[((r * 3 + oc) * 3 + co) * NB + b], relu2(acc[oc]));
}

// ---------------------------------------------------------------------------
// Kernel 5: conv4(1x1 out) + residual. 2 couts per block (8 blocks ->
// 65k threads, 14 warps/SM), float2 stores.
// ---------------------------------------------------------------------------
__global__ __launch_bounds__(128, 4) void k_conv4(
    const float* __restrict__ state, float* __restrict__ out)
{
    int tid = threadIdx.x;
    int b   = (blockIdx.x * 128 + tid) * 2;
    int cg  = blockIdx.y;              // couts 2cg, 2cg+1

    float2 a3[27];
#pragma unroll
    for (int t = 0; t < 27; t++) a3[t] = ld2(&g_a3[t * NB + b]);

    float2 acc[2];
#pragma unroll
    for (int q = 0; q < 2; q++) {
        int co = cg * 2 + q;
        acc[q] = ld2(&g_w[(P_B4 + co) * NB + b]);
#pragma unroll
        for (int t = 0; t < 27; t++)
            acc[q] = ffma2(a3[t], ld2(&g_w[(P_W4 + co * 27 + t) * NB + b]), acc[q]);
    }

    float2 s0 = ld2(&state[b * 16 + 2 * cg]);
    float2 s1 = ld2(&state[(b + 1) * 16 + 2 * cg]);
    st2(&out[b * 16 + 2 * cg],       make_float2(s0.x + acc[0].x, s0.y + acc[1].x));
    st2(&out[(b + 1) * 16 + 2 * cg], make_float2(s1.x + acc[0].y, s1.y + acc[1].y));
}

// ---------------------------------------------------------------------------
extern "C" void kernel_launch(void* const* d_in, const int* in_sizes, int n_in,
                              void* d_out, int out_size)
{
    const float* image = (const float*)d_in[0];
    const float* state = (const float*)d_in[1];
    const float* W1    = (const float*)d_in[2];
    const float* b1    = (const float*)d_in[3];
    const float* W2    = (const float*)d_in[4];
    const float* b2    = (const float*)d_in[5];
    const float* W3    = (const float*)d_in[6];
    const float* b3    = (const float*)d_in[7];
    float* out = (float*)d_out;

    k_mlp_h<<<NB / 256, 256>>>(state, W1, b1, W2, b2);
    k_mlp3 <<<dim3(NB / 128, 13), 256>>>(W3, b3);
    k_conv1<<<dim3(NB / 256, 7), 128>>>(image);
    k_conv2<<<dim3(NB / 256, 5, 3), 128>>>();
    k_conv3<<<dim3(NB / 256, 9), 128>>>();
    k_conv4<<<dim3(NB / 256, 8), 128>>>(state, out);
}